// round 5
// baseline (speedup 1.0000x reference)
#include <cuda_runtime.h>
#include <cstdint>

#define N_NODES 100000
#define N_EDGES 1600000
#define F_IN    128
#define F_H     64
#define F_OUT   16

__device__ float g_H1[N_NODES * F_H];
__device__ float g_AGG1[N_NODES * F_H];
__device__ float g_H2[N_NODES * F_OUT];

// ---- Blackwell packed fp32 helpers -----------------------------------------
__device__ __forceinline__ uint64_t bcast2(float x) {
    uint64_t r;
    asm("mov.b64 %0, {%1, %1};" : "=l"(r) : "f"(x));
    return r;
}
__device__ __forceinline__ void ffma2(uint64_t& d, uint64_t a, uint64_t b) {
    asm("fma.rn.f32x2 %0, %1, %2, %0;" : "+l"(d) : "l"(a), "l"(b));
}
__device__ __forceinline__ void unpack2(uint64_t v, float& lo, float& hi) {
    asm("mov.b64 {%0, %1}, %2;" : "=f"(lo), "=f"(hi) : "l"(v));
}

// ---------------------------------------------------------------------------
// K1: H1 = X @ W1  (100000x128 @ 128x64), f32x2 FFMA2.
// Block: 256 thr, 64-row x 64-col tile; thread = 2 rows x 8 cols.
// Also zeroes the block's AGG1 tile (replaces k_init part 1).
// ---------------------------------------------------------------------------
__global__ __launch_bounds__(256) void k_gemm1(const float* __restrict__ X,
                                               const float* __restrict__ W1) {
    __shared__ float Xs[64][132];      // pad 4 floats: kills a-load bank conflicts
    __shared__ float Ws[128][64];
    const int t  = threadIdx.x;
    const int r0 = blockIdx.x * 64;

    // zero AGG1 tile for rows r0..r0+63 (4 float4 per thread)
    {
        float4 z = make_float4(0.f, 0.f, 0.f, 0.f);
#pragma unroll
        for (int i = 0; i < 4; i++) {
            int idx = i * 256 + t;            // 0..1023 float4s
            int row = idx >> 4, c4 = idx & 15;
            if (r0 + row < N_NODES)
                *(float4*)(g_AGG1 + (size_t)(r0 + row) * F_H + c4 * 4) = z;
        }
    }

    // stage W1 (2048 float4)
    {
        const float4* W4  = (const float4*)W1;
        float4*       Ws4 = (float4*)Ws;
#pragma unroll
        for (int i = 0; i < 8; i++) Ws4[i * 256 + t] = W4[i * 256 + t];
    }
    // stage X tile: 64 rows * 32 float4
    {
#pragma unroll
        for (int i = 0; i < 8; i++) {
            int idx = i * 256 + t;            // 0..2047
            int row = idx >> 5, c4 = idx & 31;
            float4 v = make_float4(0.f, 0.f, 0.f, 0.f);
            if (r0 + row < N_NODES)
                v = *(const float4*)(X + (size_t)(r0 + row) * F_IN + c4 * 4);
            *(float4*)&Xs[row][c4 * 4] = v;
        }
    }
    __syncthreads();

    const int ry = t >> 3;        // 0..31 -> rows ry*2, ry*2+1
    const int tx = t & 7;         // cols tx*8 .. tx*8+7
    uint64_t acc0[4] = {0, 0, 0, 0};
    uint64_t acc1[4] = {0, 0, 0, 0};

#pragma unroll 8
    for (int k = 0; k < 128; k++) {
        const uint64_t* brow = (const uint64_t*)&Ws[k][tx * 8];
        uint64_t b0 = brow[0], b1 = brow[1], b2 = brow[2], b3 = brow[3];
        uint64_t a0 = bcast2(Xs[ry * 2 + 0][k]);
        uint64_t a1 = bcast2(Xs[ry * 2 + 1][k]);
        ffma2(acc0[0], a0, b0); ffma2(acc0[1], a0, b1);
        ffma2(acc0[2], a0, b2); ffma2(acc0[3], a0, b3);
        ffma2(acc1[0], a1, b0); ffma2(acc1[1], a1, b1);
        ffma2(acc1[2], a1, b2); ffma2(acc1[3], a1, b3);
    }

    int r = r0 + ry * 2;
#pragma unroll
    for (int rr = 0; rr < 2; rr++) {
        if (r + rr >= N_NODES) break;
        uint64_t* acc = rr ? acc1 : acc0;
        float f[8];
        unpack2(acc[0], f[0], f[1]); unpack2(acc[1], f[2], f[3]);
        unpack2(acc[2], f[4], f[5]); unpack2(acc[3], f[6], f[7]);
        float* o = g_H1 + (size_t)(r + rr) * F_H + tx * 8;
        *(float4*)(o + 0) = make_float4(f[0], f[1], f[2], f[3]);
        *(float4*)(o + 4) = make_float4(f[4], f[5], f[6], f[7]);
    }
}

// ---------------------------------------------------------------------------
// K2: AGG1[dst] += H1[src] * w.  4 threads/edge, 4 float4 chunks per thread.
// ---------------------------------------------------------------------------
__global__ __launch_bounds__(256) void k_scatter1(const int* __restrict__ src,
                                                  const int* __restrict__ dst,
                                                  const float* __restrict__ w) {
    const long long idx = (long long)blockIdx.x * 256 + threadIdx.x;
    const int e    = (int)(idx >> 2);
    const int part = (int)idx & 3;
    if (e >= N_EDGES) return;
    const int   s  = src[e];
    const int   d  = dst[e];
    const float ww = w[e];
    const float* ps = g_H1 + (size_t)s * F_H + part * 4;
    float*       pd = g_AGG1 + (size_t)d * F_H + part * 4;
    float4 v0 = *(const float4*)(ps +  0);
    float4 v1 = *(const float4*)(ps + 16);
    float4 v2 = *(const float4*)(ps + 32);
    float4 v3 = *(const float4*)(ps + 48);
    asm volatile("red.global.add.v4.f32 [%0], {%1,%2,%3,%4};" ::
                 "l"(pd +  0), "f"(v0.x * ww), "f"(v0.y * ww), "f"(v0.z * ww), "f"(v0.w * ww) : "memory");
    asm volatile("red.global.add.v4.f32 [%0], {%1,%2,%3,%4};" ::
                 "l"(pd + 16), "f"(v1.x * ww), "f"(v1.y * ww), "f"(v1.z * ww), "f"(v1.w * ww) : "memory");
    asm volatile("red.global.add.v4.f32 [%0], {%1,%2,%3,%4};" ::
                 "l"(pd + 32), "f"(v2.x * ww), "f"(v2.y * ww), "f"(v2.z * ww), "f"(v2.w * ww) : "memory");
    asm volatile("red.global.add.v4.f32 [%0], {%1,%2,%3,%4};" ::
                 "l"(pd + 48), "f"(v3.x * ww), "f"(v3.y * ww), "f"(v3.z * ww), "f"(v3.w * ww) : "memory");
}

// ---------------------------------------------------------------------------
// K3: H2 = relu(AGG1 + b1) @ W2  (100000x64 @ 64x16).
// Block: 256 thr, 128-node tile; thread = 2 rows x 4 cols.
// Also writes out = b2 for its nodes (replaces k_init part 2).
// ---------------------------------------------------------------------------
__global__ __launch_bounds__(256) void k_gemm2(const float* __restrict__ b1,
                                               const float* __restrict__ W2,
                                               const float* __restrict__ b2,
                                               float* __restrict__ out) {
    __shared__ float Hs[128][65];
    __shared__ float Ws2[64 * 16];
    const int t  = threadIdx.x;
    const int r0 = blockIdx.x * 128;

    // init out tile to b2 (512 float4s)
    {
        float4 b2v[4];
#pragma unroll
        for (int i = 0; i < 4; i++) b2v[i] = *(const float4*)(b2 + i * 4);
#pragma unroll
        for (int i = 0; i < 2; i++) {
            int idx = i * 256 + t;            // 0..511 float4s
            int row = idx >> 2, c4 = idx & 3;
            if (r0 + row < N_NODES)
                *(float4*)(out + (size_t)(r0 + row) * F_OUT + c4 * 4) = b2v[c4];
        }
    }

    // stage W2 (1024 floats)
#pragma unroll
    for (int i = 0; i < 4; i++) Ws2[i * 256 + t] = W2[i * 256 + t];

    // stage relu(AGG1 + b1): 128 rows x 64 cols
#pragma unroll
    for (int i = 0; i < 32; i++) {
        int idx = i * 256 + t;
        int row = idx >> 6, col = idx & 63;
        float v = 0.f;
        if (r0 + row < N_NODES)
            v = fmaxf(g_AGG1[(size_t)(r0 + row) * F_H + col] + b1[col], 0.f);
        Hs[row][col] = v;
    }
    __syncthreads();

    const int ry = t >> 2;        // 0..63 -> rows ry*2, ry*2+1
    const int tx = t & 3;         // cols tx*4..+3
    float acc0[4] = {0, 0, 0, 0};
    float acc1[4] = {0, 0, 0, 0};
#pragma unroll 8
    for (int k = 0; k < 64; k++) {
        float4 b = *(const float4*)&Ws2[k * 16 + tx * 4];
        float a0 = Hs[ry * 2 + 0][k];
        float a1 = Hs[ry * 2 + 1][k];
        acc0[0] = fmaf(a0, b.x, acc0[0]); acc0[1] = fmaf(a0, b.y, acc0[1]);
        acc0[2] = fmaf(a0, b.z, acc0[2]); acc0[3] = fmaf(a0, b.w, acc0[3]);
        acc1[0] = fmaf(a1, b.x, acc1[0]); acc1[1] = fmaf(a1, b.y, acc1[1]);
        acc1[2] = fmaf(a1, b.z, acc1[2]); acc1[3] = fmaf(a1, b.w, acc1[3]);
    }
    int r = r0 + ry * 2;
    if (r < N_NODES)
        *(float4*)(g_H2 + (size_t)r * F_OUT + tx * 4) =
            make_float4(acc0[0], acc0[1], acc0[2], acc0[3]);
    if (r + 1 < N_NODES)
        *(float4*)(g_H2 + (size_t)(r + 1) * F_OUT + tx * 4) =
            make_float4(acc1[0], acc1[1], acc1[2], acc1[3]);
}

// ---------------------------------------------------------------------------
// K4: out[dst] += H2[src] * w.  4 threads/edge, 1 float4 each.
// ---------------------------------------------------------------------------
__global__ __launch_bounds__(256) void k_scatter2(const int* __restrict__ src,
                                                  const int* __restrict__ dst,
                                                  const float* __restrict__ w,
                                                  float* __restrict__ out) {
    const long long idx = (long long)blockIdx.x * 256 + threadIdx.x;
    const int e    = (int)(idx >> 2);
    const int part = (int)idx & 3;
    if (e >= N_EDGES) return;
    const int   s  = src[e];
    const int   d  = dst[e];
    const float ww = w[e];
    const float4 v = *(const float4*)(g_H2 + (size_t)s * F_OUT + part * 4);
    float* p = out + (size_t)d * F_OUT + part * 4;
    asm volatile("red.global.add.v4.f32 [%0], {%1,%2,%3,%4};" ::
                 "l"(p), "f"(v.x * ww), "f"(v.y * ww), "f"(v.z * ww), "f"(v.w * ww)
                 : "memory");
}

// ---------------------------------------------------------------------------
// Inputs: 0:X 1:edge_weight 2:W1 3:b1 4:W2 5:b2 6:edge_src 7:edge_dst
// ---------------------------------------------------------------------------
extern "C" void kernel_launch(void* const* d_in, const int* in_sizes, int n_in,
                              void* d_out, int out_size) {
    const float* X  = (const float*)d_in[0];
    const float* ew = (const float*)d_in[1];
    const float* W1 = (const float*)d_in[2];
    const float* b1 = (const float*)d_in[3];
    const float* W2 = (const float*)d_in[4];
    const float* b2 = (const float*)d_in[5];
    const int* esrc = (const int*)d_in[6];
    const int* edst = (const int*)d_in[7];
    float* out = (float*)d_out;

    k_gemm1<<<(N_NODES + 63) / 64, 256>>>(X, W1);
    k_scatter1<<<(N_EDGES * 4 + 255) / 256, 256>>>(esrc, edst, ew);
    k_gemm2<<<(N_NODES + 127) / 128, 256>>>(b1, W2, b2, out);
    k_scatter2<<<(N_EDGES * 4 + 255) / 256, 256>>>(esrc, edst, ew, out);
}

// round 6
// speedup vs baseline: 1.1774x; 1.1774x over previous
#include <cuda_runtime.h>
#include <cstdint>

#define N_NODES 100000
#define N_EDGES 1600000
#define F_IN    128
#define F_H     64
#define F_OUT   16

__device__ float g_H1[N_NODES * F_H];
__device__ float g_AGG1[N_NODES * F_H];
__device__ float g_H2[N_NODES * F_OUT];

// ---- Blackwell packed fp32 helpers -----------------------------------------
__device__ __forceinline__ uint64_t bcast2(float x) {
    uint64_t r;
    asm("mov.b64 %0, {%1, %1};" : "=l"(r) : "f"(x));
    return r;
}
__device__ __forceinline__ void ffma2(uint64_t& d, uint64_t a, uint64_t b) {
    asm("fma.rn.f32x2 %0, %1, %2, %0;" : "+l"(d) : "l"(a), "l"(b));
}
__device__ __forceinline__ void unpack2(uint64_t v, float& lo, float& hi) {
    asm("mov.b64 {%0, %1}, %2;" : "=f"(lo), "=f"(hi) : "l"(v));
}

// ---------------------------------------------------------------------------
// K1: H1 = X @ W1  (100000x128 @ 128x64), f32x2 FFMA2.
// 128-row tile / block (256 thr). Thread = 4 rows x 8 cols.
// A streamed from global into registers (rows block-exclusive, 8-lane bcast),
// only W1 (32KB) staged in smem -> LDS = 1.0 B/FMA.
// Also zeroes the block's AGG1 tile.
// ---------------------------------------------------------------------------
__global__ __launch_bounds__(256) void k_gemm1(const float* __restrict__ X,
                                               const float* __restrict__ W1) {
    __shared__ float Ws[128][64];   // 32 KB
    const int t  = threadIdx.x;
    const int r0 = blockIdx.x * 128;

    // zero AGG1 tile: 128 rows * 16 float4 = 2048 float4
    {
        float4 z = make_float4(0.f, 0.f, 0.f, 0.f);
#pragma unroll
        for (int i = 0; i < 8; i++) {
            int idx = i * 256 + t;
            int row = idx >> 4, c4 = idx & 15;
            if (r0 + row < N_NODES)
                *(float4*)(g_AGG1 + (size_t)(r0 + row) * F_H + c4 * 4) = z;
        }
    }
    // stage W1 (2048 float4)
    {
        const float4* W4  = (const float4*)W1;
        float4*       Ws4 = (float4*)Ws;
#pragma unroll
        for (int i = 0; i < 8; i++) Ws4[i * 256 + t] = W4[i * 256 + t];
    }
    __syncthreads();

    const int ry    = t >> 3;        // 0..31 -> rows ry*4 .. ry*4+3
    const int tx    = t & 7;         // cols tx*8 .. tx*8+7
    const int rbase = r0 + ry * 4;

    const float4* xrow[4];
#pragma unroll
    for (int r = 0; r < 4; r++) {
        int rr = rbase + r;
        if (rr >= N_NODES) rr = N_NODES - 1;   // clamp: computed but not stored
        xrow[r] = (const float4*)(X + (size_t)rr * F_IN);
    }

    uint64_t acc[4][4];
#pragma unroll
    for (int r = 0; r < 4; r++)
#pragma unroll
        for (int c = 0; c < 4; c++) acc[r][c] = 0ull;

#pragma unroll 2
    for (int kc = 0; kc < 32; kc++) {          // kc = float4 chunk of k
        float4 a4[4];
#pragma unroll
        for (int r = 0; r < 4; r++) a4[r] = xrow[r][kc];
#pragma unroll
        for (int kk = 0; kk < 4; kk++) {
            const int k = kc * 4 + kk;
            const uint64_t* brow = (const uint64_t*)&Ws[k][tx * 8];
            uint64_t b0 = brow[0], b1 = brow[1], b2 = brow[2], b3 = brow[3];
#pragma unroll
            for (int r = 0; r < 4; r++) {
                float av = (kk == 0) ? a4[r].x : (kk == 1) ? a4[r].y
                         : (kk == 2) ? a4[r].z : a4[r].w;
                uint64_t a = bcast2(av);
                ffma2(acc[r][0], a, b0); ffma2(acc[r][1], a, b1);
                ffma2(acc[r][2], a, b2); ffma2(acc[r][3], a, b3);
            }
        }
    }

#pragma unroll
    for (int r = 0; r < 4; r++) {
        int rr = rbase + r;
        if (rr < N_NODES) {
            float f[8];
            unpack2(acc[r][0], f[0], f[1]); unpack2(acc[r][1], f[2], f[3]);
            unpack2(acc[r][2], f[4], f[5]); unpack2(acc[r][3], f[6], f[7]);
            float* o = g_H1 + (size_t)rr * F_H + tx * 8;
            *(float4*)(o + 0) = make_float4(f[0], f[1], f[2], f[3]);
            *(float4*)(o + 4) = make_float4(f[4], f[5], f[6], f[7]);
        }
    }
}

// ---------------------------------------------------------------------------
// K2: AGG1[dst] += H1[src] * w.  16 lanes/edge, 1 float4 each (R3 mapping:
// warp touches 2 contiguous 256B segments on both gather and RED).
// ---------------------------------------------------------------------------
__global__ __launch_bounds__(256) void k_scatter1(const int* __restrict__ src,
                                                  const int* __restrict__ dst,
                                                  const float* __restrict__ w) {
    const long long idx = (long long)blockIdx.x * 256 + threadIdx.x;
    const int e    = (int)(idx >> 4);
    const int part = (int)idx & 15;
    if (e >= N_EDGES) return;
    const int   s  = src[e];
    const int   d  = dst[e];
    const float ww = w[e];
    const float4 v = *(const float4*)(g_H1 + (size_t)s * F_H + part * 4);
    float* p = g_AGG1 + (size_t)d * F_H + part * 4;
    asm volatile("red.global.add.v4.f32 [%0], {%1,%2,%3,%4};" ::
                 "l"(p), "f"(v.x * ww), "f"(v.y * ww), "f"(v.z * ww), "f"(v.w * ww)
                 : "memory");
}

// ---------------------------------------------------------------------------
// K3: H2 = relu(AGG1 + b1) @ W2  (100000x64 @ 64x16).
// 128-node tile / block; thread = 2 rows x 4 cols. Writes out = b2 too.
// ---------------------------------------------------------------------------
__global__ __launch_bounds__(256) void k_gemm2(const float* __restrict__ b1,
                                               const float* __restrict__ W2,
                                               const float* __restrict__ b2,
                                               float* __restrict__ out) {
    __shared__ float Hs[128][65];
    __shared__ float Ws2[64 * 16];
    const int t  = threadIdx.x;
    const int r0 = blockIdx.x * 128;

    // init out tile to b2 (512 float4s)
    {
        float4 b2v[4];
#pragma unroll
        for (int i = 0; i < 4; i++) b2v[i] = *(const float4*)(b2 + i * 4);
#pragma unroll
        for (int i = 0; i < 2; i++) {
            int idx = i * 256 + t;
            int row = idx >> 2, c4 = idx & 3;
            if (r0 + row < N_NODES)
                *(float4*)(out + (size_t)(r0 + row) * F_OUT + c4 * 4) = b2v[c4];
        }
    }

    // stage W2 (1024 floats)
#pragma unroll
    for (int i = 0; i < 4; i++) Ws2[i * 256 + t] = W2[i * 256 + t];

    // stage relu(AGG1 + b1): 128 rows x 64 cols
#pragma unroll
    for (int i = 0; i < 32; i++) {
        int idx = i * 256 + t;
        int row = idx >> 6, col = idx & 63;
        float v = 0.f;
        if (r0 + row < N_NODES)
            v = fmaxf(g_AGG1[(size_t)(r0 + row) * F_H + col] + b1[col], 0.f);
        Hs[row][col] = v;
    }
    __syncthreads();

    const int ry = t >> 2;        // rows ry*2, ry*2+1
    const int tx = t & 3;         // cols tx*4..+3
    float acc0[4] = {0, 0, 0, 0};
    float acc1[4] = {0, 0, 0, 0};
#pragma unroll 8
    for (int k = 0; k < 64; k++) {
        float4 b = *(const float4*)&Ws2[k * 16 + tx * 4];
        float a0 = Hs[ry * 2 + 0][k];
        float a1 = Hs[ry * 2 + 1][k];
        acc0[0] = fmaf(a0, b.x, acc0[0]); acc0[1] = fmaf(a0, b.y, acc0[1]);
        acc0[2] = fmaf(a0, b.z, acc0[2]); acc0[3] = fmaf(a0, b.w, acc0[3]);
        acc1[0] = fmaf(a1, b.x, acc1[0]); acc1[1] = fmaf(a1, b.y, acc1[1]);
        acc1[2] = fmaf(a1, b.z, acc1[2]); acc1[3] = fmaf(a1, b.w, acc1[3]);
    }
    int r = r0 + ry * 2;
    if (r < N_NODES)
        *(float4*)(g_H2 + (size_t)r * F_OUT + tx * 4) =
            make_float4(acc0[0], acc0[1], acc0[2], acc0[3]);
    if (r + 1 < N_NODES)
        *(float4*)(g_H2 + (size_t)(r + 1) * F_OUT + tx * 4) =
            make_float4(acc1[0], acc1[1], acc1[2], acc1[3]);
}

// ---------------------------------------------------------------------------
// K4: out[dst] += H2[src] * w.  4 lanes/edge, 1 float4 each.
// ---------------------------------------------------------------------------
__global__ __launch_bounds__(256) void k_scatter2(const int* __restrict__ src,
                                                  const int* __restrict__ dst,
                                                  const float* __restrict__ w,
                                                  float* __restrict__ out) {
    const long long idx = (long long)blockIdx.x * 256 + threadIdx.x;
    const int e    = (int)(idx >> 2);
    const int part = (int)idx & 3;
    if (e >= N_EDGES) return;
    const int   s  = src[e];
    const int   d  = dst[e];
    const float ww = w[e];
    const float4 v = *(const float4*)(g_H2 + (size_t)s * F_OUT + part * 4);
    float* p = out + (size_t)d * F_OUT + part * 4;
    asm volatile("red.global.add.v4.f32 [%0], {%1,%2,%3,%4};" ::
                 "l"(p), "f"(v.x * ww), "f"(v.y * ww), "f"(v.z * ww), "f"(v.w * ww)
                 : "memory");
}

// ---------------------------------------------------------------------------
// Inputs: 0:X 1:edge_weight 2:W1 3:b1 4:W2 5:b2 6:edge_src 7:edge_dst
// ---------------------------------------------------------------------------
extern "C" void kernel_launch(void* const* d_in, const int* in_sizes, int n_in,
                              void* d_out, int out_size) {
    const float* X  = (const float*)d_in[0];
    const float* ew = (const float*)d_in[1];
    const float* W1 = (const float*)d_in[2];
    const float* b1 = (const float*)d_in[3];
    const float* W2 = (const float*)d_in[4];
    const float* b2 = (const float*)d_in[5];
    const int* esrc = (const int*)d_in[6];
    const int* edst = (const int*)d_in[7];
    float* out = (float*)d_out;

    k_gemm1<<<(N_NODES + 127) / 128, 256>>>(X, W1);
    k_scatter1<<<(N_EDGES * 16) / 256, 256>>>(esrc, edst, ew);
    k_gemm2<<<(N_NODES + 127) / 128, 256>>>(b1, W2, b2, out);
    k_scatter2<<<(N_EDGES * 4) / 256, 256>>>(esrc, edst, ew, out);
}

// round 7
// speedup vs baseline: 1.3870x; 1.1780x over previous
#include <cuda_runtime.h>
#include <cstdint>

#define N_NODES 100000
#define N_EDGES 1600000
#define F_IN    128
#define F_H     64
#define F_OUT   16
#define SCAN_B  512
#define NB_SCAN ((N_NODES + SCAN_B - 1) / SCAN_B)   // 196

__device__ float g_H1[N_NODES * F_H];
__device__ float g_AGG1[N_NODES * F_H];   // relu(A@H1 + b1)
__device__ float g_H2[N_NODES * F_OUT];
__device__ int   g_cnt[N_NODES];
__device__ int   g_excl[N_NODES];
__device__ int   g_rowptr[N_NODES + 1];
__device__ int   g_cursor[N_NODES];
__device__ int   g_bsum[256];
__device__ uint2 g_sorted[N_EDGES];       // (src, w) sorted by dst

// ---- Blackwell packed fp32 helpers -----------------------------------------
__device__ __forceinline__ uint64_t bcast2(float x) {
    uint64_t r; asm("mov.b64 %0, {%1, %1};" : "=l"(r) : "f"(x)); return r;
}
__device__ __forceinline__ void ffma2(uint64_t& d, uint64_t a, uint64_t b) {
    asm("fma.rn.f32x2 %0, %1, %2, %0;" : "+l"(d) : "l"(a), "l"(b));
}
__device__ __forceinline__ void unpack2(uint64_t v, float& lo, float& hi) {
    asm("mov.b64 {%0, %1}, %2;" : "=f"(lo), "=f"(hi) : "l"(v));
}

// ---------------------------------------------------------------------------
// K1: H1 = X @ W1  (f32x2). 128-row tile/block, thread = 4 rows x 8 cols.
// Also zeroes g_cnt (must complete before k_hist; stream order guarantees it).
// ---------------------------------------------------------------------------
__global__ __launch_bounds__(256) void k_gemm1(const float* __restrict__ X,
                                               const float* __restrict__ W1) {
    __shared__ float Ws[128][64];
    const int t  = threadIdx.x;
    const int r0 = blockIdx.x * 128;

    {   // zero histogram counters (grid covers >= N_NODES threads)
        int idx = blockIdx.x * 256 + t;
        if (idx < N_NODES) g_cnt[idx] = 0;
    }
    {   // stage W1
        const float4* W4  = (const float4*)W1;
        float4*       Ws4 = (float4*)Ws;
#pragma unroll
        for (int i = 0; i < 8; i++) Ws4[i * 256 + t] = W4[i * 256 + t];
    }
    __syncthreads();

    const int ry    = t >> 3;
    const int tx    = t & 7;
    const int rbase = r0 + ry * 4;

    const float4* xrow[4];
#pragma unroll
    for (int r = 0; r < 4; r++) {
        int rr = rbase + r;
        if (rr >= N_NODES) rr = N_NODES - 1;
        xrow[r] = (const float4*)(X + (size_t)rr * F_IN);
    }

    uint64_t acc[4][4];
#pragma unroll
    for (int r = 0; r < 4; r++)
#pragma unroll
        for (int c = 0; c < 4; c++) acc[r][c] = 0ull;

#pragma unroll 2
    for (int kc = 0; kc < 32; kc++) {
        float4 a4[4];
#pragma unroll
        for (int r = 0; r < 4; r++) a4[r] = xrow[r][kc];
#pragma unroll
        for (int kk = 0; kk < 4; kk++) {
            const int k = kc * 4 + kk;
            const uint64_t* brow = (const uint64_t*)&Ws[k][tx * 8];
            uint64_t b0 = brow[0], b1 = brow[1], b2 = brow[2], b3 = brow[3];
#pragma unroll
            for (int r = 0; r < 4; r++) {
                float av = (kk == 0) ? a4[r].x : (kk == 1) ? a4[r].y
                         : (kk == 2) ? a4[r].z : a4[r].w;
                uint64_t a = bcast2(av);
                ffma2(acc[r][0], a, b0); ffma2(acc[r][1], a, b1);
                ffma2(acc[r][2], a, b2); ffma2(acc[r][3], a, b3);
            }
        }
    }

#pragma unroll
    for (int r = 0; r < 4; r++) {
        int rr = rbase + r;
        if (rr < N_NODES) {
            float f[8];
            unpack2(acc[r][0], f[0], f[1]); unpack2(acc[r][1], f[2], f[3]);
            unpack2(acc[r][2], f[4], f[5]); unpack2(acc[r][3], f[6], f[7]);
            float* o = g_H1 + (size_t)rr * F_H + tx * 8;
            *(float4*)(o + 0) = make_float4(f[0], f[1], f[2], f[3]);
            *(float4*)(o + 4) = make_float4(f[4], f[5], f[6], f[7]);
        }
    }
}

// ---------------------------------------------------------------------------
// CSC build: histogram -> scan -> permute
// ---------------------------------------------------------------------------
__global__ __launch_bounds__(256) void k_hist(const int* __restrict__ dst) {
    int e = blockIdx.x * 256 + threadIdx.x;
    if (e < N_EDGES) atomicAdd(&g_cnt[dst[e]], 1);
}

__global__ __launch_bounds__(SCAN_B) void k_scan_block() {
    __shared__ int s[SCAN_B];
    const int t   = threadIdx.x;
    const int idx = blockIdx.x * SCAN_B + t;
    int v = (idx < N_NODES) ? g_cnt[idx] : 0;
    s[t] = v;
    __syncthreads();
#pragma unroll
    for (int off = 1; off < SCAN_B; off <<= 1) {
        int x = (t >= off) ? s[t - off] : 0;
        __syncthreads();
        if (t >= off) s[t] += x;
        __syncthreads();
    }
    if (idx < N_NODES) g_excl[idx] = s[t] - v;   // exclusive within block
    if (t == SCAN_B - 1) g_bsum[blockIdx.x] = s[t];
}

__global__ __launch_bounds__(256) void k_scan_top() {
    __shared__ int s[256];
    const int t = threadIdx.x;
    int v = (t < NB_SCAN) ? g_bsum[t] : 0;
    s[t] = v;
    __syncthreads();
#pragma unroll
    for (int off = 1; off < 256; off <<= 1) {
        int x = (t >= off) ? s[t - off] : 0;
        __syncthreads();
        if (t >= off) s[t] += x;
        __syncthreads();
    }
    if (t < NB_SCAN) g_bsum[t] = s[t] - v;       // exclusive block offsets
}

__global__ __launch_bounds__(256) void k_scan_add() {
    int idx = blockIdx.x * 256 + threadIdx.x;
    if (idx < N_NODES) {
        int r = g_excl[idx] + g_bsum[idx / SCAN_B];
        g_rowptr[idx] = r;
        g_cursor[idx] = r;
    }
    if (idx == 0) g_rowptr[N_NODES] = N_EDGES;
}

__global__ __launch_bounds__(256) void k_permute(const int* __restrict__ src,
                                                 const int* __restrict__ dst,
                                                 const float* __restrict__ w) {
    int e = blockIdx.x * 256 + threadIdx.x;
    if (e >= N_EDGES) return;
    int d   = dst[e];
    int pos = atomicAdd(&g_cursor[d], 1);
    g_sorted[pos] = make_uint2((unsigned)src[e], __float_as_uint(w[e]));
}

// ---------------------------------------------------------------------------
// K-agg1: AGG1[n] = relu(b1 + sum_{e in col(n)} w_e * H1[src_e]).
// 16 threads per node (one float4 chunk each). Warp-uniform edge loop.
// ---------------------------------------------------------------------------
__global__ __launch_bounds__(256) void k_agg1(const float* __restrict__ b1) {
    const int id   = blockIdx.x * 256 + threadIdx.x;   // grid covers exactly N_NODES*16
    const int node = id >> 4;
    const int ch   = id & 15;

    const int beg = g_rowptr[node];
    const int n   = g_rowptr[node + 1] - beg;
    const int m   = __reduce_max_sync(0xffffffffu, n);

    const float4* __restrict__ H1v = (const float4*)g_H1;
    float4 acc = make_float4(0.f, 0.f, 0.f, 0.f);
    for (int i = 0; i < m; i++) {
        if (i < n) {
            uint2 ev = g_sorted[beg + i];
            float ww = __uint_as_float(ev.y);
            float4 v = __ldg(&H1v[(size_t)ev.x * 16 + ch]);
            acc.x = fmaf(v.x, ww, acc.x);
            acc.y = fmaf(v.y, ww, acc.y);
            acc.z = fmaf(v.z, ww, acc.z);
            acc.w = fmaf(v.w, ww, acc.w);
        }
    }
    float4 bv = *(const float4*)(b1 + ch * 4);
    acc.x = fmaxf(acc.x + bv.x, 0.f);
    acc.y = fmaxf(acc.y + bv.y, 0.f);
    acc.z = fmaxf(acc.z + bv.z, 0.f);
    acc.w = fmaxf(acc.w + bv.w, 0.f);
    *(float4*)(g_AGG1 + (size_t)node * F_H + ch * 4) = acc;
}

// ---------------------------------------------------------------------------
// K-gemm2: H2 = AGG1 @ W2  (AGG1 already relu+bias'd). 128-node tile.
// ---------------------------------------------------------------------------
__global__ __launch_bounds__(256) void k_gemm2(const float* __restrict__ W2) {
    __shared__ float Hs[128][65];
    __shared__ float Ws2[64 * 16];
    const int t  = threadIdx.x;
    const int r0 = blockIdx.x * 128;

#pragma unroll
    for (int i = 0; i < 4; i++) Ws2[i * 256 + t] = W2[i * 256 + t];

#pragma unroll
    for (int i = 0; i < 32; i++) {
        int idx = i * 256 + t;
        int row = idx >> 6, col = idx & 63;
        float v = 0.f;
        if (r0 + row < N_NODES) v = g_AGG1[(size_t)(r0 + row) * F_H + col];
        Hs[row][col] = v;
    }
    __syncthreads();

    const int ry = t >> 2;
    const int tx = t & 3;
    float acc0[4] = {0, 0, 0, 0};
    float acc1[4] = {0, 0, 0, 0};
#pragma unroll 8
    for (int k = 0; k < 64; k++) {
        float4 b = *(const float4*)&Ws2[k * 16 + tx * 4];
        float a0 = Hs[ry * 2 + 0][k];
        float a1 = Hs[ry * 2 + 1][k];
        acc0[0] = fmaf(a0, b.x, acc0[0]); acc0[1] = fmaf(a0, b.y, acc0[1]);
        acc0[2] = fmaf(a0, b.z, acc0[2]); acc0[3] = fmaf(a0, b.w, acc0[3]);
        acc1[0] = fmaf(a1, b.x, acc1[0]); acc1[1] = fmaf(a1, b.y, acc1[1]);
        acc1[2] = fmaf(a1, b.z, acc1[2]); acc1[3] = fmaf(a1, b.w, acc1[3]);
    }
    int r = r0 + ry * 2;
    if (r < N_NODES)
        *(float4*)(g_H2 + (size_t)r * F_OUT + tx * 4) =
            make_float4(acc0[0], acc0[1], acc0[2], acc0[3]);
    if (r + 1 < N_NODES)
        *(float4*)(g_H2 + (size_t)(r + 1) * F_OUT + tx * 4) =
            make_float4(acc1[0], acc1[1], acc1[2], acc1[3]);
}

// ---------------------------------------------------------------------------
// K-agg2: out[n] = b2 + sum_{e in col(n)} w_e * H2[src_e].  4 threads/node.
// ---------------------------------------------------------------------------
__global__ __launch_bounds__(256) void k_agg2(const float* __restrict__ b2,
                                              float* __restrict__ out) {
    const int id    = blockIdx.x * 256 + threadIdx.x;
    const int node  = id >> 2;
    const int ch    = id & 3;
    const bool valid = node < N_NODES;

    int beg = 0, n = 0;
    if (valid) {
        beg = g_rowptr[node];
        n   = g_rowptr[node + 1] - beg;
    }
    const int m = __reduce_max_sync(0xffffffffu, n);

    const float4* __restrict__ H2v = (const float4*)g_H2;
    float4 acc = make_float4(0.f, 0.f, 0.f, 0.f);
    for (int i = 0; i < m; i++) {
        if (i < n) {
            uint2 ev = g_sorted[beg + i];
            float ww = __uint_as_float(ev.y);
            float4 v = __ldg(&H2v[(size_t)ev.x * 4 + ch]);
            acc.x = fmaf(v.x, ww, acc.x);
            acc.y = fmaf(v.y, ww, acc.y);
            acc.z = fmaf(v.z, ww, acc.z);
            acc.w = fmaf(v.w, ww, acc.w);
        }
    }
    if (valid) {
        float4 bv = *(const float4*)(b2 + ch * 4);
        *(float4*)(out + (size_t)node * F_OUT + ch * 4) =
            make_float4(acc.x + bv.x, acc.y + bv.y, acc.z + bv.z, acc.w + bv.w);
    }
}

// ---------------------------------------------------------------------------
// Inputs: 0:X 1:edge_weight 2:W1 3:b1 4:W2 5:b2 6:edge_src 7:edge_dst
// ---------------------------------------------------------------------------
extern "C" void kernel_launch(void* const* d_in, const int* in_sizes, int n_in,
                              void* d_out, int out_size) {
    const float* X  = (const float*)d_in[0];
    const float* ew = (const float*)d_in[1];
    const float* W1 = (const float*)d_in[2];
    const float* b1 = (const float*)d_in[3];
    const float* W2 = (const float*)d_in[4];
    const float* b2 = (const float*)d_in[5];
    const int* esrc = (const int*)d_in[6];
    const int* edst = (const int*)d_in[7];
    float* out = (float*)d_out;

    k_gemm1<<<(N_NODES + 127) / 128, 256>>>(X, W1);          // also zeroes g_cnt
    k_hist<<<(N_EDGES + 255) / 256, 256>>>(edst);
    k_scan_block<<<NB_SCAN, SCAN_B>>>();
    k_scan_top<<<1, 256>>>();
    k_scan_add<<<(N_NODES + 255) / 256, 256>>>();
    k_permute<<<(N_EDGES + 255) / 256, 256>>>(esrc, edst, ew);
    k_agg1<<<(N_NODES * 16) / 256, 256>>>(b1);
    k_gemm2<<<(N_NODES + 127) / 128, 256>>>(W2);
    k_agg2<<<(N_NODES * 4 + 255) / 256, 256>>>(b2, out);
}

// round 8
// speedup vs baseline: 1.4607x; 1.0532x over previous
#include <cuda_runtime.h>
#include <cuda_fp16.h>
#include <cstdint>

#define N_NODES 100000
#define N_EDGES 1600000
#define F_IN    128
#define F_H     64
#define F_OUT   16
#define SCAN_B  512
#define NB_SCAN ((N_NODES + SCAN_B - 1) / SCAN_B)   // 196

__device__ __half g_H1h[N_NODES * F_H];    // X @ W1, fp16 (12.8 MB)
__device__ float  g_AGG1[N_NODES * F_H];   // relu(A@H1 + b1), fp32
__device__ __half g_H2h[N_NODES * F_OUT];  // fp16 (3.2 MB)
__device__ int    g_cnt[N_NODES];
__device__ int    g_excl[N_NODES];
__device__ int    g_rowptr[N_NODES + 1];
__device__ int    g_cursor[N_NODES];
__device__ int    g_bsum[256];
__device__ uint2  g_sorted[N_EDGES];       // (src, w) sorted by dst

// ---- Blackwell packed fp32 helpers -----------------------------------------
__device__ __forceinline__ uint64_t bcast2(float x) {
    uint64_t r; asm("mov.b64 %0, {%1, %1};" : "=l"(r) : "f"(x)); return r;
}
__device__ __forceinline__ void ffma2(uint64_t& d, uint64_t a, uint64_t b) {
    asm("fma.rn.f32x2 %0, %1, %2, %0;" : "+l"(d) : "l"(a), "l"(b));
}
__device__ __forceinline__ void unpack2(uint64_t v, float& lo, float& hi) {
    asm("mov.b64 {%0, %1}, %2;" : "=f"(lo), "=f"(hi) : "l"(v));
}

// ---------------------------------------------------------------------------
// K1: H1 = X @ W1 (f32x2 compute, fp16 store). 128-row tile, 4 rows x 8 cols.
// Also zeroes g_cnt.
// ---------------------------------------------------------------------------
__global__ __launch_bounds__(256) void k_gemm1(const float* __restrict__ X,
                                               const float* __restrict__ W1) {
    __shared__ float Ws[128][64];
    const int t  = threadIdx.x;
    const int r0 = blockIdx.x * 128;

    {
        int idx = blockIdx.x * 256 + t;
        if (idx < N_NODES) g_cnt[idx] = 0;
    }
    {
        const float4* W4  = (const float4*)W1;
        float4*       Ws4 = (float4*)Ws;
#pragma unroll
        for (int i = 0; i < 8; i++) Ws4[i * 256 + t] = W4[i * 256 + t];
    }
    __syncthreads();

    const int ry    = t >> 3;
    const int tx    = t & 7;
    const int rbase = r0 + ry * 4;

    const float4* xrow[4];
#pragma unroll
    for (int r = 0; r < 4; r++) {
        int rr = rbase + r;
        if (rr >= N_NODES) rr = N_NODES - 1;
        xrow[r] = (const float4*)(X + (size_t)rr * F_IN);
    }

    uint64_t acc[4][4];
#pragma unroll
    for (int r = 0; r < 4; r++)
#pragma unroll
        for (int c = 0; c < 4; c++) acc[r][c] = 0ull;

#pragma unroll 2
    for (int kc = 0; kc < 32; kc++) {
        float4 a4[4];
#pragma unroll
        for (int r = 0; r < 4; r++) a4[r] = xrow[r][kc];
#pragma unroll
        for (int kk = 0; kk < 4; kk++) {
            const int k = kc * 4 + kk;
            const uint64_t* brow = (const uint64_t*)&Ws[k][tx * 8];
            uint64_t b0 = brow[0], b1 = brow[1], b2 = brow[2], b3 = brow[3];
#pragma unroll
            for (int r = 0; r < 4; r++) {
                float av = (kk == 0) ? a4[r].x : (kk == 1) ? a4[r].y
                         : (kk == 2) ? a4[r].z : a4[r].w;
                uint64_t a = bcast2(av);
                ffma2(acc[r][0], a, b0); ffma2(acc[r][1], a, b1);
                ffma2(acc[r][2], a, b2); ffma2(acc[r][3], a, b3);
            }
        }
    }

#pragma unroll
    for (int r = 0; r < 4; r++) {
        int rr = rbase + r;
        if (rr < N_NODES) {
            float f[8];
            unpack2(acc[r][0], f[0], f[1]); unpack2(acc[r][1], f[2], f[3]);
            unpack2(acc[r][2], f[4], f[5]); unpack2(acc[r][3], f[6], f[7]);
            __half2 h[4];
            h[0] = __floats2half2_rn(f[0], f[1]);
            h[1] = __floats2half2_rn(f[2], f[3]);
            h[2] = __floats2half2_rn(f[4], f[5]);
            h[3] = __floats2half2_rn(f[6], f[7]);
            *(uint4*)(g_H1h + (size_t)rr * F_H + tx * 8) = *(uint4*)h;
        }
    }
}

// ---------------------------------------------------------------------------
// CSC build: histogram -> block scan -> (fused top-scan + add) -> permute
// ---------------------------------------------------------------------------
__global__ __launch_bounds__(256) void k_hist(const int* __restrict__ dst) {
    int e = blockIdx.x * 256 + threadIdx.x;
    if (e < N_EDGES) atomicAdd(&g_cnt[dst[e]], 1);
}

__global__ __launch_bounds__(SCAN_B) void k_scan_block() {
    __shared__ int s[SCAN_B];
    const int t   = threadIdx.x;
    const int idx = blockIdx.x * SCAN_B + t;
    int v = (idx < N_NODES) ? g_cnt[idx] : 0;
    s[t] = v;
    __syncthreads();
#pragma unroll
    for (int off = 1; off < SCAN_B; off <<= 1) {
        int x = (t >= off) ? s[t - off] : 0;
        __syncthreads();
        if (t >= off) s[t] += x;
        __syncthreads();
    }
    if (idx < N_NODES) g_excl[idx] = s[t] - v;
    if (t == SCAN_B - 1) g_bsum[blockIdx.x] = s[t];
}

// Fused: each block computes its own prefix over g_bsum, then finalizes rowptr.
__global__ __launch_bounds__(SCAN_B) void k_scan_fin() {
    __shared__ int ws[SCAN_B / 32];
    __shared__ int s_prefix;
    const int b    = blockIdx.x;
    const int t    = threadIdx.x;
    const int lane = t & 31;
    const int wid  = t >> 5;

    int v = (t < b) ? g_bsum[t] : 0;     // t < b <= 195 < 256 (g_bsum bound ok)
#pragma unroll
    for (int off = 16; off > 0; off >>= 1)
        v += __shfl_down_sync(0xffffffffu, v, off);
    if (lane == 0) ws[wid] = v;
    __syncthreads();
    if (t == 0) {
        int s = 0;
#pragma unroll
        for (int i = 0; i < SCAN_B / 32; i++) s += ws[i];
        s_prefix = s;
    }
    __syncthreads();
    const int prefix = s_prefix;

    int idx = b * SCAN_B + t;
    if (idx < N_NODES) {
        int r = g_excl[idx] + prefix;
        g_rowptr[idx] = r;
        g_cursor[idx] = r;
    }
    if (b == 0 && t == 0) g_rowptr[N_NODES] = N_EDGES;
}

__global__ __launch_bounds__(256) void k_permute(const int* __restrict__ src,
                                                 const int* __restrict__ dst,
                                                 const float* __restrict__ w) {
    int e = blockIdx.x * 256 + threadIdx.x;
    if (e >= N_EDGES) return;
    int d   = dst[e];
    int pos = atomicAdd(&g_cursor[d], 1);
    g_sorted[pos] = make_uint2((unsigned)src[e], __float_as_uint(w[e]));
}

// ---------------------------------------------------------------------------
// K-agg1: AGG1[n] = relu(b1 + sum w_e * H1[src_e]).  16 lanes/node, 4 feats
// (8B fp16) each; warp gather footprint per edge = 128B contiguous.
// Unroll-2 for two gather chains in flight.
// ---------------------------------------------------------------------------
__global__ __launch_bounds__(256) void k_agg1(const float* __restrict__ b1) {
    const int id   = blockIdx.x * 256 + threadIdx.x;
    const int node = id >> 4;
    const int ch   = id & 15;

    const int beg = g_rowptr[node];
    const int n   = g_rowptr[node + 1] - beg;
    const int m   = __reduce_max_sync(0xffffffffu, n);

    const uint2* __restrict__ H1p = (const uint2*)g_H1h;   // 8B = 4 halves
    float4 acc = make_float4(0.f, 0.f, 0.f, 0.f);

    for (int i = 0; i < m; i += 2) {
        uint2 hv0 = make_uint2(0u, 0u), hv1 = make_uint2(0u, 0u);
        float w0 = 0.f, w1 = 0.f;
        if (i < n) {
            uint2 ev = g_sorted[beg + i];
            w0  = __uint_as_float(ev.y);
            hv0 = __ldg(&H1p[(size_t)ev.x * 16 + ch]);
        }
        if (i + 1 < n) {
            uint2 ev = g_sorted[beg + i + 1];
            w1  = __uint_as_float(ev.y);
            hv1 = __ldg(&H1p[(size_t)ev.x * 16 + ch]);
        }
        {
            __half2* ph = (__half2*)&hv0;
            float2 lo = __half22float2(ph[0]);
            float2 hi = __half22float2(ph[1]);
            acc.x = fmaf(lo.x, w0, acc.x); acc.y = fmaf(lo.y, w0, acc.y);
            acc.z = fmaf(hi.x, w0, acc.z); acc.w = fmaf(hi.y, w0, acc.w);
        }
        {
            __half2* ph = (__half2*)&hv1;
            float2 lo = __half22float2(ph[0]);
            float2 hi = __half22float2(ph[1]);
            acc.x = fmaf(lo.x, w1, acc.x); acc.y = fmaf(lo.y, w1, acc.y);
            acc.z = fmaf(hi.x, w1, acc.z); acc.w = fmaf(hi.y, w1, acc.w);
        }
    }
    float4 bv = *(const float4*)(b1 + ch * 4);
    acc.x = fmaxf(acc.x + bv.x, 0.f);
    acc.y = fmaxf(acc.y + bv.y, 0.f);
    acc.z = fmaxf(acc.z + bv.z, 0.f);
    acc.w = fmaxf(acc.w + bv.w, 0.f);
    *(float4*)(g_AGG1 + (size_t)node * F_H + ch * 4) = acc;
}

// ---------------------------------------------------------------------------
// K-gemm2: H2 = AGG1 @ W2 (fp32 compute, fp16 store). 128-node tile.
// ---------------------------------------------------------------------------
__global__ __launch_bounds__(256) void k_gemm2(const float* __restrict__ W2) {
    __shared__ float Hs[128][65];
    __shared__ float Ws2[64 * 16];
    const int t  = threadIdx.x;
    const int r0 = blockIdx.x * 128;

#pragma unroll
    for (int i = 0; i < 4; i++) Ws2[i * 256 + t] = W2[i * 256 + t];

#pragma unroll
    for (int i = 0; i < 32; i++) {
        int idx = i * 256 + t;
        int row = idx >> 6, col = idx & 63;
        float v = 0.f;
        if (r0 + row < N_NODES) v = g_AGG1[(size_t)(r0 + row) * F_H + col];
        Hs[row][col] = v;
    }
    __syncthreads();

    const int ry = t >> 2;
    const int tx = t & 3;
    float acc0[4] = {0, 0, 0, 0};
    float acc1[4] = {0, 0, 0, 0};
#pragma unroll 8
    for (int k = 0; k < 64; k++) {
        float4 b = *(const float4*)&Ws2[k * 16 + tx * 4];
        float a0 = Hs[ry * 2 + 0][k];
        float a1 = Hs[ry * 2 + 1][k];
        acc0[0] = fmaf(a0, b.x, acc0[0]); acc0[1] = fmaf(a0, b.y, acc0[1]);
        acc0[2] = fmaf(a0, b.z, acc0[2]); acc0[3] = fmaf(a0, b.w, acc0[3]);
        acc1[0] = fmaf(a1, b.x, acc1[0]); acc1[1] = fmaf(a1, b.y, acc1[1]);
        acc1[2] = fmaf(a1, b.z, acc1[2]); acc1[3] = fmaf(a1, b.w, acc1[3]);
    }
    int r = r0 + ry * 2;
    if (r < N_NODES) {
        __half2 h[2] = { __floats2half2_rn(acc0[0], acc0[1]),
                         __floats2half2_rn(acc0[2], acc0[3]) };
        *(uint2*)(g_H2h + (size_t)r * F_OUT + tx * 4) = *(uint2*)h;
    }
    if (r + 1 < N_NODES) {
        __half2 h[2] = { __floats2half2_rn(acc1[0], acc1[1]),
                         __floats2half2_rn(acc1[2], acc1[3]) };
        *(uint2*)(g_H2h + (size_t)(r + 1) * F_OUT + tx * 4) = *(uint2*)h;
    }
}

// ---------------------------------------------------------------------------
// K-agg2: out[n] = b2 + sum w_e * H2[src_e].  4 lanes/node, 4 fp16 feats each.
// ---------------------------------------------------------------------------
__global__ __launch_bounds__(256) void k_agg2(const float* __restrict__ b2,
                                              float* __restrict__ out) {
    const int id     = blockIdx.x * 256 + threadIdx.x;
    const int node   = id >> 2;
    const int ch     = id & 3;
    const bool valid = node < N_NODES;

    int beg = 0, n = 0;
    if (valid) {
        beg = g_rowptr[node];
        n   = g_rowptr[node + 1] - beg;
    }
    const int m = __reduce_max_sync(0xffffffffu, n);

    const uint2* __restrict__ H2p = (const uint2*)g_H2h;
    float4 acc = make_float4(0.f, 0.f, 0.f, 0.f);

    for (int i = 0; i < m; i += 2) {
        uint2 hv0 = make_uint2(0u, 0u), hv1 = make_uint2(0u, 0u);
        float w0 = 0.f, w1 = 0.f;
        if (i < n) {
            uint2 ev = g_sorted[beg + i];
            w0  = __uint_as_float(ev.y);
            hv0 = __ldg(&H2p[(size_t)ev.x * 4 + ch]);
        }
        if (i + 1 < n) {
            uint2 ev = g_sorted[beg + i + 1];
            w1  = __uint_as_float(ev.y);
            hv1 = __ldg(&H2p[(size_t)ev.x * 4 + ch]);
        }
        {
            __half2* ph = (__half2*)&hv0;
            float2 lo = __half22float2(ph[0]);
            float2 hi = __half22float2(ph[1]);
            acc.x = fmaf(lo.x, w0, acc.x); acc.y = fmaf(lo.y, w0, acc.y);
            acc.z = fmaf(hi.x, w0, acc.z); acc.w = fmaf(hi.y, w0, acc.w);
        }
        {
            __half2* ph = (__half2*)&hv1;
            float2 lo = __half22float2(ph[0]);
            float2 hi = __half22float2(ph[1]);
            acc.x = fmaf(lo.x, w1, acc.x); acc.y = fmaf(lo.y, w1, acc.y);
            acc.z = fmaf(hi.x, w1, acc.z); acc.w = fmaf(hi.y, w1, acc.w);
        }
    }
    if (valid) {
        float4 bv = *(const float4*)(b2 + ch * 4);
        *(float4*)(out + (size_t)node * F_OUT + ch * 4) =
            make_float4(acc.x + bv.x, acc.y + bv.y, acc.z + bv.z, acc.w + bv.w);
    }
}

// ---------------------------------------------------------------------------
// Inputs: 0:X 1:edge_weight 2:W1 3:b1 4:W2 5:b2 6:edge_src 7:edge_dst
// ---------------------------------------------------------------------------
extern "C" void kernel_launch(void* const* d_in, const int* in_sizes, int n_in,
                              void* d_out, int out_size) {
    const float* X  = (const float*)d_in[0];
    const float* ew = (const float*)d_in[1];
    const float* W1 = (const float*)d_in[2];
    const float* b1 = (const float*)d_in[3];
    const float* W2 = (const float*)d_in[4];
    const float* b2 = (const float*)d_in[5];
    const int* esrc = (const int*)d_in[6];
    const int* edst = (const int*)d_in[7];
    float* out = (float*)d_out;

    k_gemm1<<<(N_NODES + 127) / 128, 256>>>(X, W1);
    k_hist<<<(N_EDGES + 255) / 256, 256>>>(edst);
    k_scan_block<<<NB_SCAN, SCAN_B>>>();
    k_scan_fin<<<NB_SCAN, SCAN_B>>>();
    k_permute<<<(N_EDGES + 255) / 256, 256>>>(esrc, edst, ew);
    k_agg1<<<(N_NODES * 16) / 256, 256>>>(b1);
    k_gemm2<<<(N_NODES + 127) / 128, 256>>>(W2);
    k_agg2<<<(N_NODES * 4 + 255) / 256, 256>>>(b2, out);
}

// round 11
// speedup vs baseline: 1.5794x; 1.0812x over previous
#include <cuda_runtime.h>
#include <cuda_fp16.h>
#include <cstdint>

#define N_NODES 100000
#define N_EDGES 1600000
#define F_IN    128
#define F_H     64
#define F_OUT   16
#define SCAN_B  512
#define NB_SCAN ((N_NODES + SCAN_B - 1) / SCAN_B)   // 196

__device__ __half g_H1h[N_NODES * F_H];
__device__ float  g_AGG1[N_NODES * F_H];
__device__ __half g_H2h[N_NODES * F_OUT];
__device__ int    g_cnt[N_NODES];
__device__ int    g_excl[N_NODES];
__device__ int    g_rowptr[N_NODES + 1];
__device__ int    g_cursor[N_NODES];
__device__ int    g_bsum[256];
__device__ uint2  g_sorted[N_EDGES];

// ---- Blackwell packed fp32 helpers -----------------------------------------
__device__ __forceinline__ uint64_t bcast2(float x) {
    uint64_t r; asm("mov.b64 %0, {%1, %1};" : "=l"(r) : "f"(x)); return r;
}
__device__ __forceinline__ void ffma2(uint64_t& d, uint64_t a, uint64_t b) {
    asm("fma.rn.f32x2 %0, %1, %2, %0;" : "+l"(d) : "l"(a), "l"(b));
}
__device__ __forceinline__ void unpack2(uint64_t v, float& lo, float& hi) {
    asm("mov.b64 {%0, %1}, %2;" : "=f"(lo), "=f"(hi) : "l"(v));
}

// ---------------------------------------------------------------------------
// K1: H1 = X @ W1 (f32x2 compute, fp16 store). 128-row tile, 4 rows x 8 cols.
// ---------------------------------------------------------------------------
__global__ __launch_bounds__(256) void k_gemm1(const float* __restrict__ X,
                                               const float* __restrict__ W1) {
    __shared__ float Ws[128][64];
    const int t  = threadIdx.x;
    const int r0 = blockIdx.x * 128;

    {
        const float4* W4  = (const float4*)W1;
        float4*       Ws4 = (float4*)Ws;
#pragma unroll
        for (int i = 0; i < 8; i++) Ws4[i * 256 + t] = W4[i * 256 + t];
    }
    __syncthreads();

    const int ry    = t >> 3;
    const int tx    = t & 7;
    const int rbase = r0 + ry * 4;

    const float4* xrow[4];
#pragma unroll
    for (int r = 0; r < 4; r++) {
        int rr = rbase + r;
        if (rr >= N_NODES) rr = N_NODES - 1;
        xrow[r] = (const float4*)(X + (size_t)rr * F_IN);
    }

    uint64_t acc[4][4];
#pragma unroll
    for (int r = 0; r < 4; r++)
#pragma unroll
        for (int c = 0; c < 4; c++) acc[r][c] = 0ull;

#pragma unroll 2
    for (int kc = 0; kc < 32; kc++) {
        float4 a4[4];
#pragma unroll
        for (int r = 0; r < 4; r++) a4[r] = xrow[r][kc];
#pragma unroll
        for (int kk = 0; kk < 4; kk++) {
            const int k = kc * 4 + kk;
            const uint64_t* brow = (const uint64_t*)&Ws[k][tx * 8];
            uint64_t b0 = brow[0], b1 = brow[1], b2 = brow[2], b3 = brow[3];
#pragma unroll
            for (int r = 0; r < 4; r++) {
                float av = (kk == 0) ? a4[r].x : (kk == 1) ? a4[r].y
                         : (kk == 2) ? a4[r].z : a4[r].w;
                uint64_t a = bcast2(av);
                ffma2(acc[r][0], a, b0); ffma2(acc[r][1], a, b1);
                ffma2(acc[r][2], a, b2); ffma2(acc[r][3], a, b3);
            }
        }
    }

#pragma unroll
    for (int r = 0; r < 4; r++) {
        int rr = rbase + r;
        if (rr < N_NODES) {
            float f[8];
            unpack2(acc[r][0], f[0], f[1]); unpack2(acc[r][1], f[2], f[3]);
            unpack2(acc[r][2], f[4], f[5]); unpack2(acc[r][3], f[6], f[7]);
            __half2 h[4];
            h[0] = __floats2half2_rn(f[0], f[1]);
            h[1] = __floats2half2_rn(f[2], f[3]);
            h[2] = __floats2half2_rn(f[4], f[5]);
            h[3] = __floats2half2_rn(f[6], f[7]);
            *(uint4*)(g_H1h + (size_t)rr * F_H + tx * 8) = *(uint4*)h;
        }
    }
}

// ---------------------------------------------------------------------------
// CSC build (runs on forked stream, parallel with gemm1)
// ---------------------------------------------------------------------------
__global__ __launch_bounds__(512) void k_zero_cnt() {
    int i = blockIdx.x * 512 + threadIdx.x;
    if (i < N_NODES) g_cnt[i] = 0;
}

__global__ __launch_bounds__(256) void k_hist(const int* __restrict__ dst) {
    int e = blockIdx.x * 256 + threadIdx.x;
    if (e < N_EDGES) atomicAdd(&g_cnt[dst[e]], 1);
}

__global__ __launch_bounds__(SCAN_B) void k_scan_block() {
    __shared__ int s[SCAN_B];
    const int t   = threadIdx.x;
    const int idx = blockIdx.x * SCAN_B + t;
    int v = (idx < N_NODES) ? g_cnt[idx] : 0;
    s[t] = v;
    __syncthreads();
#pragma unroll
    for (int off = 1; off < SCAN_B; off <<= 1) {
        int x = (t >= off) ? s[t - off] : 0;
        __syncthreads();
        if (t >= off) s[t] += x;
        __syncthreads();
    }
    if (idx < N_NODES) g_excl[idx] = s[t] - v;
    if (t == SCAN_B - 1) g_bsum[blockIdx.x] = s[t];
}

__global__ __launch_bounds__(SCAN_B) void k_scan_fin() {
    __shared__ int ws[SCAN_B / 32];
    __shared__ int s_prefix;
    const int b    = blockIdx.x;
    const int t    = threadIdx.x;
    const int lane = t & 31;
    const int wid  = t >> 5;

    int v = (t < b) ? g_bsum[t] : 0;
#pragma unroll
    for (int off = 16; off > 0; off >>= 1)
        v += __shfl_down_sync(0xffffffffu, v, off);
    if (lane == 0) ws[wid] = v;
    __syncthreads();
    if (t == 0) {
        int s = 0;
#pragma unroll
        for (int i = 0; i < SCAN_B / 32; i++) s += ws[i];
        s_prefix = s;
    }
    __syncthreads();
    const int prefix = s_prefix;

    int idx = b * SCAN_B + t;
    if (idx < N_NODES) {
        int r = g_excl[idx] + prefix;
        g_rowptr[idx] = r;
        g_cursor[idx] = r;
    }
    if (b == 0 && t == 0) g_rowptr[N_NODES] = N_EDGES;
}

__global__ __launch_bounds__(256) void k_permute(const int* __restrict__ src,
                                                 const int* __restrict__ dst,
                                                 const float* __restrict__ w) {
    int e = blockIdx.x * 256 + threadIdx.x;
    if (e >= N_EDGES) return;
    int d   = dst[e];
    int pos = atomicAdd(&g_cursor[d], 1);
    g_sorted[pos] = make_uint2((unsigned)src[e], __float_as_uint(w[e]));
}

// ---------------------------------------------------------------------------
// K-agg1: AGG1[n] = relu(b1 + sum w_e * H1[src_e]). 16 lanes/node, unroll 4.
// ---------------------------------------------------------------------------
__global__ __launch_bounds__(256) void k_agg1(const float* __restrict__ b1) {
    const int id   = blockIdx.x * 256 + threadIdx.x;
    const int node = id >> 4;
    const int ch   = id & 15;

    const int beg = g_rowptr[node];
    const int n   = g_rowptr[node + 1] - beg;
    const int m   = __reduce_max_sync(0xffffffffu, n);

    const uint2* __restrict__ H1p = (const uint2*)g_H1h;
    float4 acc = make_float4(0.f, 0.f, 0.f, 0.f);

    for (int i = 0; i < m; i += 4) {
        uint2 hv[4];
        float wv[4];
#pragma unroll
        for (int j = 0; j < 4; j++) {
            hv[j] = make_uint2(0u, 0u);
            wv[j] = 0.f;
            if (i + j < n) {
                uint2 ev = g_sorted[beg + i + j];
                wv[j] = __uint_as_float(ev.y);
                hv[j] = __ldg(&H1p[(size_t)ev.x * 16 + ch]);
            }
        }
#pragma unroll
        for (int j = 0; j < 4; j++) {
            __half2* ph = (__half2*)&hv[j];
            float2 lo = __half22float2(ph[0]);
            float2 hi = __half22float2(ph[1]);
            acc.x = fmaf(lo.x, wv[j], acc.x); acc.y = fmaf(lo.y, wv[j], acc.y);
            acc.z = fmaf(hi.x, wv[j], acc.z); acc.w = fmaf(hi.y, wv[j], acc.w);
        }
    }
    float4 bv = *(const float4*)(b1 + ch * 4);
    acc.x = fmaxf(acc.x + bv.x, 0.f);
    acc.y = fmaxf(acc.y + bv.y, 0.f);
    acc.z = fmaxf(acc.z + bv.z, 0.f);
    acc.w = fmaxf(acc.w + bv.w, 0.f);
    *(float4*)(g_AGG1 + (size_t)node * F_H + ch * 4) = acc;
}

// ---------------------------------------------------------------------------
// K-gemm2: H2 = AGG1 @ W2 (fp32 compute, fp16 store).
// ---------------------------------------------------------------------------
__global__ __launch_bounds__(256) void k_gemm2(const float* __restrict__ W2) {
    __shared__ float Hs[128][65];
    __shared__ float Ws2[64 * 16];
    const int t  = threadIdx.x;
    const int r0 = blockIdx.x * 128;

#pragma unroll
    for (int i = 0; i < 4; i++) Ws2[i * 256 + t] = W2[i * 256 + t];

#pragma unroll
    for (int i = 0; i < 32; i++) {
        int idx = i * 256 + t;
        int row = idx >> 6, col = idx & 63;
        float v = 0.f;
        if (r0 + row < N_NODES) v = g_AGG1[(size_t)(r0 + row) * F_H + col];
        Hs[row][col] = v;
    }
    __syncthreads();

    const int ry = t >> 2;
    const int tx = t & 3;
    float acc0[4] = {0, 0, 0, 0};
    float acc1[4] = {0, 0, 0, 0};
#pragma unroll 8
    for (int k = 0; k < 64; k++) {
        float4 b = *(const float4*)&Ws2[k * 16 + tx * 4];
        float a0 = Hs[ry * 2 + 0][k];
        float a1 = Hs[ry * 2 + 1][k];
        acc0[0] = fmaf(a0, b.x, acc0[0]); acc0[1] = fmaf(a0, b.y, acc0[1]);
        acc0[2] = fmaf(a0, b.z, acc0[2]); acc0[3] = fmaf(a0, b.w, acc0[3]);
        acc1[0] = fmaf(a1, b.x, acc1[0]); acc1[1] = fmaf(a1, b.y, acc1[1]);
        acc1[2] = fmaf(a1, b.z, acc1[2]); acc1[3] = fmaf(a1, b.w, acc1[3]);
    }
    int r = r0 + ry * 2;
    if (r < N_NODES) {
        __half2 h[2] = { __floats2half2_rn(acc0[0], acc0[1]),
                         __floats2half2_rn(acc0[2], acc0[3]) };
        *(uint2*)(g_H2h + (size_t)r * F_OUT + tx * 4) = *(uint2*)h;
    }
    if (r + 1 < N_NODES) {
        __half2 h[2] = { __floats2half2_rn(acc1[0], acc1[1]),
                         __floats2half2_rn(acc1[2], acc1[3]) };
        *(uint2*)(g_H2h + (size_t)(r + 1) * F_OUT + tx * 4) = *(uint2*)h;
    }
}

// ---------------------------------------------------------------------------
// K-agg2: out[n] = b2 + sum w_e * H2[src_e]. 4 lanes/node, unroll 4.
// ---------------------------------------------------------------------------
__global__ __launch_bounds__(256) void k_agg2(const float* __restrict__ b2,
                                              float* __restrict__ out) {
    const int id     = blockIdx.x * 256 + threadIdx.x;
    const int node   = id >> 2;
    const int ch     = id & 3;
    const bool valid = node < N_NODES;

    int beg = 0, n = 0;
    if (valid) {
        beg = g_rowptr[node];
        n   = g_rowptr[node + 1] - beg;
    }
    const int m = __reduce_max_sync(0xffffffffu, n);

    const uint2* __restrict__ H2p = (const uint2*)g_H2h;
    float4 acc = make_float4(0.f, 0.f, 0.f, 0.f);

    for (int i = 0; i < m; i += 4) {
        uint2 hv[4];
        float wv[4];
#pragma unroll
        for (int j = 0; j < 4; j++) {
            hv[j] = make_uint2(0u, 0u);
            wv[j] = 0.f;
            if (i + j < n) {
                uint2 ev = g_sorted[beg + i + j];
                wv[j] = __uint_as_float(ev.y);
                hv[j] = __ldg(&H2p[(size_t)ev.x * 4 + ch]);
            }
        }
#pragma unroll
        for (int j = 0; j < 4; j++) {
            __half2* ph = (__half2*)&hv[j];
            float2 lo = __half22float2(ph[0]);
            float2 hi = __half22float2(ph[1]);
            acc.x = fmaf(lo.x, wv[j], acc.x); acc.y = fmaf(lo.y, wv[j], acc.y);
            acc.z = fmaf(hi.x, wv[j], acc.z); acc.w = fmaf(hi.y, wv[j], acc.w);
        }
    }
    if (valid) {
        float4 bv = *(const float4*)(b2 + ch * 4);
        *(float4*)(out + (size_t)node * F_OUT + ch * 4) =
            make_float4(acc.x + bv.x, acc.y + bv.y, acc.z + bv.z, acc.w + bv.w);
    }
}

// ---------------------------------------------------------------------------
// Launch: fork CSC build onto a second stream, parallel with gemm1.
// Stream/events are created once (host-side objects; no device allocation).
// Work launched per call is identical every call.
// ---------------------------------------------------------------------------
extern "C" void kernel_launch(void* const* d_in, const int* in_sizes, int n_in,
                              void* d_out, int out_size) {
    const float* X  = (const float*)d_in[0];
    const float* ew = (const float*)d_in[1];
    const float* W1 = (const float*)d_in[2];
    const float* b1 = (const float*)d_in[3];
    const float* W2 = (const float*)d_in[4];
    const float* b2 = (const float*)d_in[5];
    const int* esrc = (const int*)d_in[6];
    const int* edst = (const int*)d_in[7];
    float* out = (float*)d_out;

    static cudaStream_t s2 = nullptr;
    static cudaEvent_t evFork = nullptr, evJoin = nullptr;
    if (s2 == nullptr) {
        cudaStreamCreateWithFlags(&s2, cudaStreamNonBlocking);
        cudaEventCreateWithFlags(&evFork, cudaEventDisableTiming);
        cudaEventCreateWithFlags(&evJoin, cudaEventDisableTiming);
    }

    // fork: CSC build on s2 (depends only on edge inputs)
    cudaEventRecord(evFork, 0);
    cudaStreamWaitEvent(s2, evFork, 0);
    k_zero_cnt<<<(N_NODES + 511) / 512, 512, 0, s2>>>();
    k_hist<<<(N_EDGES + 255) / 256, 256, 0, s2>>>(edst);
    k_scan_block<<<NB_SCAN, SCAN_B, 0, s2>>>();
    k_scan_fin<<<NB_SCAN, SCAN_B, 0, s2>>>();
    k_permute<<<(N_EDGES + 255) / 256, 256, 0, s2>>>(esrc, edst, ew);
    cudaEventRecord(evJoin, s2);

    // main: gemm1 runs concurrently with the CSC build
    k_gemm1<<<(N_NODES + 127) / 128, 256>>>(X, W1);

    // join, then the dependent chain
    cudaStreamWaitEvent(0, evJoin, 0);
    k_agg1<<<(N_NODES * 16) / 256, 256>>>(b1);
    k_gemm2<<<(N_NODES + 127) / 128, 256>>>(W2);
    k_agg2<<<(N_NODES * 4 + 255) / 256, 256>>>(b2, out);
}

// round 14
// speedup vs baseline: 1.6292x; 1.0315x over previous
#include <cuda_runtime.h>
#include <cuda_fp16.h>
#include <cstdint>

#define N_NODES 100000
#define N_EDGES 1600000
#define F_IN    128
#define F_H     64
#define F_OUT   16
#define SCAN_B  512
#define NB_SCAN ((N_NODES + SCAN_B - 1) / SCAN_B)   // 196

__device__ __half g_H1h[N_NODES * F_H];
__device__ __half g_H2h[N_NODES * F_OUT];
__device__ int    g_cnt[N_NODES];
__device__ int    g_excl[N_NODES];
__device__ int    g_rowptr[N_NODES + 1];
__device__ int    g_cursor[N_NODES];
__device__ int    g_bsum[256];
__device__ uint2  g_sorted[N_EDGES];

// ---- Blackwell packed fp32 helpers -----------------------------------------
__device__ __forceinline__ uint64_t bcast2(float x) {
    uint64_t r; asm("mov.b64 %0, {%1, %1};" : "=l"(r) : "f"(x)); return r;
}
__device__ __forceinline__ void ffma2(uint64_t& d, uint64_t a, uint64_t b) {
    asm("fma.rn.f32x2 %0, %1, %2, %0;" : "+l"(d) : "l"(a), "l"(b));
}
__device__ __forceinline__ void unpack2(uint64_t v, float& lo, float& hi) {
    asm("mov.b64 {%0, %1}, %2;" : "=f"(lo), "=f"(hi) : "l"(v));
}

// ---------------------------------------------------------------------------
// K1: H1 = X @ W1 (f32x2 compute, fp16 store). 128-row tile, 4 rows x 8 cols.
// ---------------------------------------------------------------------------
__global__ __launch_bounds__(256) void k_gemm1(const float* __restrict__ X,
                                               const float* __restrict__ W1) {
    __shared__ float Ws[128][64];
    const int t  = threadIdx.x;
    const int r0 = blockIdx.x * 128;

    {
        const float4* W4  = (const float4*)W1;
        float4*       Ws4 = (float4*)Ws;
#pragma unroll
        for (int i = 0; i < 8; i++) Ws4[i * 256 + t] = W4[i * 256 + t];
    }
    __syncthreads();

    const int ry    = t >> 3;
    const int tx    = t & 7;
    const int rbase = r0 + ry * 4;

    const float4* xrow[4];
#pragma unroll
    for (int r = 0; r < 4; r++) {
        int rr = rbase + r;
        if (rr >= N_NODES) rr = N_NODES - 1;
        xrow[r] = (const float4*)(X + (size_t)rr * F_IN);
    }

    uint64_t acc[4][4];
#pragma unroll
    for (int r = 0; r < 4; r++)
#pragma unroll
        for (int c = 0; c < 4; c++) acc[r][c] = 0ull;

#pragma unroll 2
    for (int kc = 0; kc < 32; kc++) {
        float4 a4[4];
#pragma unroll
        for (int r = 0; r < 4; r++) a4[r] = xrow[r][kc];
#pragma unroll
        for (int kk = 0; kk < 4; kk++) {
            const int k = kc * 4 + kk;
            const uint64_t* brow = (const uint64_t*)&Ws[k][tx * 8];
            uint64_t b0 = brow[0], b1 = brow[1], b2 = brow[2], b3 = brow[3];
#pragma unroll
            for (int r = 0; r < 4; r++) {
                float av = (kk == 0) ? a4[r].x : (kk == 1) ? a4[r].y
                         : (kk == 2) ? a4[r].z : a4[r].w;
                uint64_t a = bcast2(av);
                ffma2(acc[r][0], a, b0); ffma2(acc[r][1], a, b1);
                ffma2(acc[r][2], a, b2); ffma2(acc[r][3], a, b3);
            }
        }
    }

#pragma unroll
    for (int r = 0; r < 4; r++) {
        int rr = rbase + r;
        if (rr < N_NODES) {
            float f[8];
            unpack2(acc[r][0], f[0], f[1]); unpack2(acc[r][1], f[2], f[3]);
            unpack2(acc[r][2], f[4], f[5]); unpack2(acc[r][3], f[6], f[7]);
            __half2 h[4];
            h[0] = __floats2half2_rn(f[0], f[1]);
            h[1] = __floats2half2_rn(f[2], f[3]);
            h[2] = __floats2half2_rn(f[4], f[5]);
            h[3] = __floats2half2_rn(f[6], f[7]);
            *(uint4*)(g_H1h + (size_t)rr * F_H + tx * 8) = *(uint4*)h;
        }
    }
}

// ---------------------------------------------------------------------------
// CSC build (forked stream, parallel with gemm1)
// ---------------------------------------------------------------------------
__global__ __launch_bounds__(512) void k_zero_cnt() {
    int i = blockIdx.x * 512 + threadIdx.x;
    if (i < N_NODES) g_cnt[i] = 0;
}

__global__ __launch_bounds__(256) void k_hist(const int* __restrict__ dst) {
    int i = blockIdx.x * 256 + threadIdx.x;       // i indexes int4 chunks
    if (i < N_EDGES / 4) {
        int4 d = ((const int4*)dst)[i];
        atomicAdd(&g_cnt[d.x], 1);
        atomicAdd(&g_cnt[d.y], 1);
        atomicAdd(&g_cnt[d.z], 1);
        atomicAdd(&g_cnt[d.w], 1);
    }
}

__global__ __launch_bounds__(SCAN_B) void k_scan_block() {
    __shared__ int s[SCAN_B];
    const int t   = threadIdx.x;
    const int idx = blockIdx.x * SCAN_B + t;
    int v = (idx < N_NODES) ? g_cnt[idx] : 0;
    s[t] = v;
    __syncthreads();
#pragma unroll
    for (int off = 1; off < SCAN_B; off <<= 1) {
        int x = (t >= off) ? s[t - off] : 0;
        __syncthreads();
        if (t >= off) s[t] += x;
        __syncthreads();
    }
    if (idx < N_NODES) g_excl[idx] = s[t] - v;
    if (t == SCAN_B - 1) g_bsum[blockIdx.x] = s[t];
}

__global__ __launch_bounds__(SCAN_B) void k_scan_fin() {
    __shared__ int ws[SCAN_B / 32];
    __shared__ int s_prefix;
    const int b    = blockIdx.x;
    const int t    = threadIdx.x;
    const int lane = t & 31;
    const int wid  = t >> 5;

    int v = (t < b) ? g_bsum[t] : 0;
#pragma unroll
    for (int off = 16; off > 0; off >>= 1)
        v += __shfl_down_sync(0xffffffffu, v, off);
    if (lane == 0) ws[wid] = v;
    __syncthreads();
    if (t == 0) {
        int s = 0;
#pragma unroll
        for (int i = 0; i < SCAN_B / 32; i++) s += ws[i];
        s_prefix = s;
    }
    __syncthreads();
    const int prefix = s_prefix;

    int idx = b * SCAN_B + t;
    if (idx < N_NODES) {
        int r = g_excl[idx] + prefix;
        g_rowptr[idx] = r;
        g_cursor[idx] = r;
    }
    if (b == 0 && t == 0) g_rowptr[N_NODES] = N_EDGES;
}

__global__ __launch_bounds__(256) void k_permute(const int* __restrict__ src,
                                                 const int* __restrict__ dst,
                                                 const float* __restrict__ w) {
    int e = blockIdx.x * 256 + threadIdx.x;
    if (e >= N_EDGES) return;
    int d   = dst[e];
    int pos = atomicAdd(&g_cursor[d], 1);
    g_sorted[pos] = make_uint2((unsigned)src[e], __float_as_uint(w[e]));
}

// ---------------------------------------------------------------------------
// K-agg1f: fused aggregate + relu + bias + GEMM2.
// Block = 256 thr = 16 nodes x 16 lanes.
// Phase 1: 16 lanes/node gather-accumulate relu(b1 + sum w*H1[src]) -> smem.
// Phase 2: thread (node, o) computes H2[node][o] = vec . W2[:,o] via LDS.128.
// ---------------------------------------------------------------------------
__global__ __launch_bounds__(256) void k_agg1f(const float* __restrict__ b1,
                                               const float* __restrict__ W2) {
    __shared__ float Hs[16][68];    // relu vec per node (68: pad, 16B-aligned rows)
    __shared__ float W2t[16][68];   // W2 transposed: W2t[o][k]
    const int t    = threadIdx.x;
    const int node = blockIdx.x * 16 + (t >> 4);
    const int ch   = t & 15;

    // stage W2 transposed (1024 elems, 4/thread)
#pragma unroll
    for (int i = 0; i < 4; i++) {
        int idx = i * 256 + t;
        W2t[idx & 15][idx >> 4] = W2[idx];
    }

    const int beg = g_rowptr[node];
    const int n   = g_rowptr[node + 1] - beg;
    const int m   = __reduce_max_sync(0xffffffffu, n);

    const uint2* __restrict__ H1p = (const uint2*)g_H1h;
    float4 acc = make_float4(0.f, 0.f, 0.f, 0.f);

    for (int i = 0; i < m; i += 4) {
        uint2 hv[4];
        float wv[4];
#pragma unroll
        for (int j = 0; j < 4; j++) {
            hv[j] = make_uint2(0u, 0u);
            wv[j] = 0.f;
            if (i + j < n) {
                uint2 ev = g_sorted[beg + i + j];
                wv[j] = __uint_as_float(ev.y);
                hv[j] = __ldg(&H1p[(size_t)ev.x * 16 + ch]);
            }
        }
#pragma unroll
        for (int j = 0; j < 4; j++) {
            __half2* ph = (__half2*)&hv[j];
            float2 lo = __half22float2(ph[0]);
            float2 hi = __half22float2(ph[1]);
            acc.x = fmaf(lo.x, wv[j], acc.x); acc.y = fmaf(lo.y, wv[j], acc.y);
            acc.z = fmaf(hi.x, wv[j], acc.z); acc.w = fmaf(hi.y, wv[j], acc.w);
        }
    }
    {
        float4 bv = *(const float4*)(b1 + ch * 4);
        acc.x = fmaxf(acc.x + bv.x, 0.f);
        acc.y = fmaxf(acc.y + bv.y, 0.f);
        acc.z = fmaxf(acc.z + bv.z, 0.f);
        acc.w = fmaxf(acc.w + bv.w, 0.f);
        *(float4*)&Hs[t >> 4][ch * 4] = acc;
    }
    __syncthreads();

    // phase 2: thread (nd, o): H2[node][o] = Hs[nd][:] . W2t[o][:]
    {
        const int nd = t >> 4;       // same node as phase 1
        const int o  = ch;
        const float4* hrow = (const float4*)&Hs[nd][0];
        const float4* wrow = (const float4*)&W2t[o][0];
        float s = 0.f;
#pragma unroll
        for (int k4 = 0; k4 < 16; k4++) {
            float4 a = hrow[k4];
            float4 b = wrow[k4];
            s = fmaf(a.x, b.x, s); s = fmaf(a.y, b.y, s);
            s = fmaf(a.z, b.z, s); s = fmaf(a.w, b.w, s);
        }
        g_H2h[(size_t)node * F_OUT + o] = __float2half_rn(s);
    }
}

// ---------------------------------------------------------------------------
// K-agg2: out[n] = b2 + sum w_e * H2[src_e]. 4 lanes/node, unroll 8.
// ---------------------------------------------------------------------------
__global__ __launch_bounds__(256) void k_agg2(const float* __restrict__ b2,
                                              float* __restrict__ out) {
    const int id     = blockIdx.x * 256 + threadIdx.x;
    const int node   = id >> 2;
    const int ch     = id & 3;
    const bool valid = node < N_NODES;

    int beg = 0, n = 0;
    if (valid) {
        beg = g_rowptr[node];
        n   = g_rowptr[node + 1] - beg;
    }
    const int m = __reduce_max_sync(0xffffffffu, n);

    const uint2* __restrict__ H2p = (const uint2*)g_H2h;
    float4 acc = make_float4(0.f, 0.f, 0.f, 0.f);

    for (int i = 0; i < m; i += 8) {
        uint2 hv[8];
        float wv[8];
#pragma unroll
        for (int j = 0; j < 8; j++) {
            hv[j] = make_uint2(0u, 0u);
            wv[j] = 0.f;
            if (i + j < n) {
                uint2 ev = g_sorted[beg + i + j];
                wv[j] = __uint_as_float(ev.y);
                hv[j] = __ldg(&H2p[(size_t)ev.x * 4 + ch]);
            }
        }
#pragma unroll
        for (int j = 0; j < 8; j++) {
            __half2* ph = (__half2*)&hv[j];
            float2 lo = __half22float2(ph[0]);
            float2 hi = __half22float2(ph[1]);
            acc.x = fmaf(lo.x, wv[j], acc.x); acc.y = fmaf(lo.y, wv[j], acc.y);
            acc.z = fmaf(hi.x, wv[j], acc.z); acc.w = fmaf(hi.y, wv[j], acc.w);
        }
    }
    if (valid) {
        float4 bv = *(const float4*)(b2 + ch * 4);
        *(float4*)(out + (size_t)node * F_OUT + ch * 4) =
            make_float4(acc.x + bv.x, acc.y + bv.y, acc.z + bv.z, acc.w + bv.w);
    }
}

// ---------------------------------------------------------------------------
// Launch: fork CSC build onto a second stream, parallel with gemm1.
// ---------------------------------------------------------------------------
extern "C" void kernel_launch(void* const* d_in, const int* in_sizes, int n_in,
                              void* d_out, int out_size) {
    const float* X  = (const float*)d_in[0];
    const float* ew = (const float*)d_in[1];
    const float* W1 = (const float*)d_in[2];
    const float* b1 = (const float*)d_in[3];
    const float* W2 = (const float*)d_in[4];
    const float* b2 = (const float*)d_in[5];
    const int* esrc = (const int*)d_in[6];
    const int* edst = (const int*)d_in[7];
    float* out = (float*)d_out;

    static cudaStream_t s2 = nullptr;
    static cudaEvent_t evFork = nullptr, evJoin = nullptr;
    if (s2 == nullptr) {
        cudaStreamCreateWithFlags(&s2, cudaStreamNonBlocking);
        cudaEventCreateWithFlags(&evFork, cudaEventDisableTiming);
        cudaEventCreateWithFlags(&evJoin, cudaEventDisableTiming);
    }

    cudaEventRecord(evFork, 0);
    cudaStreamWaitEvent(s2, evFork, 0);
    k_zero_cnt<<<(N_NODES + 511) / 512, 512, 0, s2>>>();
    k_hist<<<(N_EDGES / 4 + 255) / 256, 256, 0, s2>>>(edst);
    k_scan_block<<<NB_SCAN, SCAN_B, 0, s2>>>();
    k_scan_fin<<<NB_SCAN, SCAN_B, 0, s2>>>();
    k_permute<<<(N_EDGES + 255) / 256, 256, 0, s2>>>(esrc, edst, ew);
    cudaEventRecord(evJoin, s2);

    k_gemm1<<<(N_NODES + 127) / 128, 256>>>(X, W1);

    cudaStreamWaitEvent(0, evJoin, 0);
    k_agg1f<<<(N_NODES + 15) / 16, 256>>>(b1, W2);
    k_agg2<<<(N_NODES * 4 + 255) / 256, 256>>>(b2, out);
}